// round 7
// baseline (speedup 1.0000x reference)
#include <cuda_runtime.h>
#include <cstdint>

// Output: R[b, s, 64, 64] fp32, 16384 matrices of 16 KB each.
// Per matrix: 32 diagonal 2x2 rotation blocks (128 nonzero floats), zeros
// elsewhere; nonzero locations identical for every matrix.
//
// Direct-store variant: one CTA (256 threads) per matrix. Each thread owns
// float4 slots tid + 256k (k=0..3): 4 unconditional coalesced zero STG.128
// plus at most one predicated (sin,cos)-pair overwrite. No SMEM staging, no
// fences/TMA — tests whether the raw STG->L2->DRAM path beats the TMA bounce.

static constexpr unsigned THREADS = 256;

__global__ void __launch_bounds__(THREADS) rope2d_stg_kernel(
    const float* __restrict__ spa,   // (n_mat, 2)
    float4* __restrict__ out)        // (n_mat, 1024) float4 view
{
    unsigned tid = threadIdx.x;
    unsigned bs  = blockIdx.x;

    // ---- match decode: slot w = tid + 256k -> row = 16k + (tid>>4),
    // f4col = tid & 15. Pair slot iff f4col == row>>2 = 4k + (tid>>6).
    unsigned f4   = tid & 15u;
    int      diff = (int)f4 - (int)(tid >> 6);
    bool   match  = (diff >= 0) && ((diff & 3) == 0);
    unsigned km   = (unsigned)diff >> 2;            // matching k (0..3)
    unsigned row  = 16u * km + (tid >> 4);          // matched output row

    // ---- pair value (meaningful only when match) --------------------------
    float4 pv = make_float4(0.f, 0.f, 0.f, 0.f);
    if (match) {
        float2 xy = *reinterpret_cast<const float2*>(spa + (size_t)bs * 2u);
        unsigned h = row >> 1;                      // 0..31
        float coord = (h & 16u) ? xy.y : xy.x;
        // inv_freq = 10000^(-(h%16)/16) = 2^(-(h%16)*log2(10000)/16)
        float invf = exp2f(-(float)(h & 15u) * (13.287712379549449f / 16.0f));
        float s, c;
        __sincosf(coord * invf, &s, &c);
        float a, b;
        if (row & 1u) { a = s; b = c;  }            // odd row:  (sin, cos)
        else          { a = c; b = -s; }            // even row: (cos, -sin)
        if (row & 2u) { pv.z = a; pv.w = b; }       // pair at lanes 2,3
        else          { pv.x = a; pv.y = b; }       // pair at lanes 0,1
    }

    // ---- stores: 4 unconditional zeros + <=1 predicated overwrite ---------
    const float4 z = make_float4(0.f, 0.f, 0.f, 0.f);
    float4* base = out + (size_t)bs * 1024u + tid;
    #pragma unroll
    for (unsigned k = 0; k < 4; k++)
        base[256u * k] = z;
    if (match)
        base[256u * km] = pv;   // same thread, same address: ordered after zero
}

extern "C" void kernel_launch(void* const* d_in, const int* in_sizes, int n_in,
                              void* d_out, int out_size)
{
    const float* spa = (const float*)d_in[0];
    float4* out = (float4*)d_out;

    unsigned n_mat = (unsigned)(out_size / 4096);   // 16384
    rope2d_stg_kernel<<<n_mat, THREADS>>>(spa, out);
}

// round 8
// speedup vs baseline: 1.0520x; 1.0520x over previous
#include <cuda_runtime.h>
#include <cstdint>

// Output: R[b, s, 64, 64] fp32, 16384 matrices of 16 KB each.
// Per matrix: 32 diagonal 2x2 rotation blocks (128 nonzero floats), zeros
// elsewhere; nonzero locations identical across matrices.
//
// Direct streaming-store kernel: one CTA (256 threads) per matrix. Each
// thread owns float4 slots tid + 256k (k=0..3); exactly one slot per
// matching thread holds the (sin,cos) pair, selected in-register (no
// zero-then-overwrite). All stores use st.global.cs (evict-first) since the
// output is a write-once stream that should not occupy L2.

static constexpr unsigned THREADS = 256;

__global__ void __launch_bounds__(THREADS) rope2d_stgcs_kernel(
    const float* __restrict__ spa,   // (n_mat, 2)
    float4* __restrict__ out)        // (n_mat, 1024) float4 view
{
    unsigned tid = threadIdx.x;
    unsigned bs  = blockIdx.x;

    // ---- match decode: slot w = tid + 256k -> row = 16k + (tid>>4),
    // f4col = tid & 15. Pair slot iff f4col == 4k + (tid>>6).
    unsigned f4   = tid & 15u;
    int      diff = (int)f4 - (int)(tid >> 6);
    bool   match  = (diff >= 0) && ((diff & 3) == 0);
    unsigned km   = (unsigned)diff >> 2;            // matching k (0..3)
    unsigned row  = 16u * km + (tid >> 4);          // matched output row

    // ---- pair value (zeros when no match) ---------------------------------
    float4 pv = make_float4(0.f, 0.f, 0.f, 0.f);
    if (match) {
        float2 xy = *reinterpret_cast<const float2*>(spa + (size_t)bs * 2u);
        unsigned h = row >> 1;                      // 0..31
        float coord = (h & 16u) ? xy.y : xy.x;
        // inv_freq = 10000^(-(h%16)/16) = 2^(-(h%16)*log2(10000)/16)
        float invf = exp2f(-(float)(h & 15u) * (13.287712379549449f / 16.0f));
        float s, c;
        __sincosf(coord * invf, &s, &c);
        float a, b;
        if (row & 1u) { a = s; b = c;  }            // odd row:  (sin, cos)
        else          { a = c; b = -s; }            // even row: (cos, -sin)
        if (row & 2u) { pv.z = a; pv.w = b; }       // pair at lanes 2,3
        else          { pv.x = a; pv.y = b; }       // pair at lanes 0,1
    }

    // ---- 4 streaming stores, pair value selected in-register --------------
    const float4 z = make_float4(0.f, 0.f, 0.f, 0.f);
    float4* base = out + (size_t)bs * 1024u + tid;
    #pragma unroll
    for (unsigned k = 0; k < 4; k++) {
        float4 v = (match && k == km) ? pv : z;
        __stcs(base + 256u * k, v);                 // st.global.cs.v4 (evict-first)
    }
}

extern "C" void kernel_launch(void* const* d_in, const int* in_sizes, int n_in,
                              void* d_out, int out_size)
{
    const float* spa = (const float*)d_in[0];
    float4* out = (float4*)d_out;

    unsigned n_mat = (unsigned)(out_size / 4096);   // 16384
    rope2d_stgcs_kernel<<<n_mat, THREADS>>>(spa, out);
}